// round 5
// baseline (speedup 1.0000x reference)
#include <cuda_runtime.h>
#include <cstdint>

// LSTM  B=64, T=1024, D=512, U=512, OUT=4
#define BATCH    64
#define TSTEPS   1024
#define DIN      512
#define UNITS    512
#define FOURU    2048
#define NCTA     128
#define TPB      256
#define NBG      4
#define GROUP_CTAS 32

// smem layout (floats)
#define SM_R4     0        // [128 kq][16 u][16 e]  e=g*4+kl : 32768
#define SM_H4     32768    // [128 kq][68 pad]  (b*4+kl)     : 8704
#define SM_XZ     41472    // [2][4 g][16 u][17 pad]         : 2176
#define SM_FLOATS 43648
#define SM_BYTES  (SM_FLOATS * 4)

__device__ float    g_xz[(size_t)BATCH * TSTEPS * FOURU];  // 512 MB
__device__ float    g_h[2][BATCH][UNITS];                  // batch-major
__device__ unsigned g_flags[NBG][GROUP_CTAS];              // 128B per group

typedef unsigned long long u64t;
__device__ __forceinline__ u64t splat2(float x) {
    u64t r; asm("mov.b64 %0, {%1, %1};" : "=l"(r) : "f"(x)); return r;
}
__device__ __forceinline__ void ffma2(u64t& d, u64t a, u64t b) {
    asm("fma.rn.f32x2 %0, %1, %2, %0;" : "+l"(d) : "l"(a), "l"(b));
}
__device__ __forceinline__ float2 unpack2(u64t v) {
    float2 f; asm("mov.b64 {%0, %1}, %2;" : "=f"(f.x), "=f"(f.y) : "l"(v)); return f;
}
__device__ __forceinline__ float fsig(float x) {
    return __fdividef(1.f, 1.f + __expf(-x));
}
__device__ __forceinline__ float ftanh(float x) {
    return 1.f - __fdividef(2.f, __expf(2.f * x) + 1.f);
}

__global__ void init_kernel() {
    int i = blockIdx.x * blockDim.x + threadIdx.x;
    if (i < 2 * BATCH * UNITS) ((float*)g_h)[i] = 0.f;
    if (i < NBG * GROUP_CTAS) ((unsigned*)g_flags)[i] = 0u;
}

// -------- input GEMM (unchanged from R2): g_xz = A @ W + bias ---------------
__global__ __launch_bounds__(256) void sgemm_bias(
    const float* __restrict__ A, const float* __restrict__ W,
    const float* __restrict__ bias)
{
    __shared__ float As[8][128];
    __shared__ float Bs[8][128];

    const int tid = threadIdx.x;
    const int tx = tid & 15, ty = tid >> 4;
    const int bx = blockIdx.x, by = blockIdx.y;
    const int aRow = tid >> 1, aK = (tid & 1) * 4;
    const int wK = tid >> 5, wN = (tid & 31) * 4;

    const float* Aptr = A + (size_t)(by * 128 + aRow) * DIN + aK;
    const float* Wptr = W + (size_t)wK * FOURU + bx * 128 + wN;

    float4 aReg = *(const float4*)Aptr;
    float4 wReg = *(const float4*)Wptr;

    u64t acc[8][4];
#pragma unroll
    for (int m = 0; m < 8; m++)
#pragma unroll
        for (int n = 0; n < 4; n++) acc[m][n] = 0ull;

    for (int kt = 0; kt < DIN / 8; kt++) {
        As[aK + 0][aRow] = aReg.x;
        As[aK + 1][aRow] = aReg.y;
        As[aK + 2][aRow] = aReg.z;
        As[aK + 3][aRow] = aReg.w;
        *(float4*)&Bs[wK][wN] = wReg;
        __syncthreads();

        if (kt < DIN / 8 - 1) {
            aReg = *(const float4*)(Aptr + (kt + 1) * 8);
            wReg = *(const float4*)(Wptr + (size_t)(kt + 1) * 8 * FOURU);
        }

#pragma unroll
        for (int k = 0; k < 8; k++) {
            float4 a0 = *(const float4*)&As[k][ty * 8];
            float4 a1 = *(const float4*)&As[k][ty * 8 + 4];
            ulonglong2 b01 = *(const ulonglong2*)&Bs[k][tx * 8];
            ulonglong2 b23 = *(const ulonglong2*)&Bs[k][tx * 8 + 4];
            float av[8] = {a0.x, a0.y, a0.z, a0.w, a1.x, a1.y, a1.z, a1.w};
#pragma unroll
            for (int m = 0; m < 8; m++) {
                u64t s = splat2(av[m]);
                ffma2(acc[m][0], b01.x, s);
                ffma2(acc[m][1], b01.y, s);
                ffma2(acc[m][2], b23.x, s);
                ffma2(acc[m][3], b23.y, s);
            }
        }
        __syncthreads();
    }

    float4 bias0 = *(const float4*)&bias[bx * 128 + tx * 8];
    float4 bias1 = *(const float4*)&bias[bx * 128 + tx * 8 + 4];
#pragma unroll
    for (int m = 0; m < 8; m++) {
        float* Cp = g_xz + (size_t)(by * 128 + ty * 8 + m) * FOURU + bx * 128 + tx * 8;
        float2 p0 = unpack2(acc[m][0]);
        float2 p1 = unpack2(acc[m][1]);
        float2 p2 = unpack2(acc[m][2]);
        float2 p3 = unpack2(acc[m][3]);
        float4 o0 = make_float4(p0.x + bias0.x, p0.y + bias0.y,
                                p1.x + bias0.z, p1.y + bias0.w);
        float4 o1 = make_float4(p2.x + bias1.x, p2.y + bias1.y,
                                p3.x + bias1.z, p3.y + bias1.w);
        __stcs((float4*)Cp, o0);
        __stcs((float4*)(Cp + 4), o1);
    }
}

// -------- persistent LSTM recurrence ---------------------------------------
// CTA (ug,bg): units [16ug,+16), batches [16bg,+16). Thread: u_l=tid>>4,
// b_l=tid&15. Flag-line barrier per batch-group, two-phase staged h.
__global__ __launch_bounds__(TPB, 1) void lstm_recur(const float* __restrict__ R)
{
    extern __shared__ float sm[];
    float* R4  = sm + SM_R4;
    float* h4  = sm + SM_H4;
    float* xzs = sm + SM_XZ;

    const int tid = threadIdx.x;
    const int ug = blockIdx.x >> 2, bg = blockIdx.x & 3;
    const int u0 = ug * 16, b0 = bg * 16;
    const int b_l = tid & 15, u_l = tid >> 4;

    // R4[kq][u][g*4+kl] = R[(kq*4+kl)][g*512+u0+u]
    for (int i = tid; i < 32768; i += TPB) {
        int kq = i >> 8, u = (i >> 4) & 15, e = i & 15, g = e >> 2, kl = e & 3;
        R4[i] = R[(size_t)(kq * 4 + kl) * FOURU + g * UNITS + u0 + u];
    }

    // xz staging: thread -> (pb, pg, pq); layout [2][g*272 + row*17 + b]
    const int pb = tid >> 4, pg = (tid >> 2) & 3, pq = tid & 3;
    const float* xz_thread = g_xz + (size_t)(b0 + pb) * TSTEPS * FOURU
                             + pg * UNITS + u0 + pq * 4;
    {
        float4 v = __ldcs((const float4*)xz_thread);
        float vv[4] = {v.x, v.y, v.z, v.w};
#pragma unroll
        for (int j = 0; j < 4; j++)
            xzs[pg * 272 + (pq * 4 + j) * 17 + pb] = vv[j];
    }
    __syncthreads();

    // h staging mapping: sb = batch (0..15), kqb = quad column (0..15)
    const int sb = tid >> 4, kqb = tid & 15;
    unsigned* myflag = &g_flags[bg][ug];
    const unsigned* flagline = &g_flags[bg][0];

    float c_state = 0.f;

    for (int t = 0; t < TSTEPS; t++) {
        float4 xnext = make_float4(0.f, 0.f, 0.f, 0.f);
        if (t + 1 < TSTEPS)
            xnext = __ldcs((const float4*)(xz_thread + (size_t)(t + 1) * FOURU));

        // issue all 8 h loads (coalesced, batch-major), MLP=8
        const float* hsrc = &g_h[t & 1][b0 + sb][0];
        float4 hq[8];
#pragma unroll
        for (int r = 0; r < 8; r++)
            hq[r] = __ldcg((const float4*)(hsrc + (kqb + 16 * r) * 4));

        // stage half0 (kq < 64), pad-68 rows -> STS.128, ~2-way max
#pragma unroll
        for (int r = 0; r < 4; r++)
            *(float4*)&h4[(kqb + 16 * r) * 68 + sb * 4] = hq[r];
        __syncthreads();

        u64t a0 = 0ull, a1 = 0ull, a2 = 0ull, a3 = 0ull;
        const float* hrow = h4 + b_l * 4;
        const float* rrow = R4 + u_l * 16;
#pragma unroll 8
        for (int kq = 0; kq < 64; kq++) {
            ulonglong2 hh = *(const ulonglong2*)(hrow + kq * 68);
            ulonglong2 r0 = *(const ulonglong2*)(rrow + kq * 256);
            ulonglong2 r1 = *(const ulonglong2*)(rrow + kq * 256 + 4);
            ulonglong2 r2 = *(const ulonglong2*)(rrow + kq * 256 + 8);
            ulonglong2 r3 = *(const ulonglong2*)(rrow + kq * 256 + 12);
            ffma2(a0, r0.x, hh.x); ffma2(a0, r0.y, hh.y);
            ffma2(a1, r1.x, hh.x); ffma2(a1, r1.y, hh.y);
            ffma2(a2, r2.x, hh.x); ffma2(a2, r2.y, hh.y);
            ffma2(a3, r3.x, hh.x); ffma2(a3, r3.y, hh.y);
        }

        // stage half1 (loads have landed during half0 compute)
#pragma unroll
        for (int r = 4; r < 8; r++)
            *(float4*)&h4[(kqb + 16 * r) * 68 + sb * 4] = hq[r];
        __syncthreads();

#pragma unroll 8
        for (int kq = 64; kq < 128; kq++) {
            ulonglong2 hh = *(const ulonglong2*)(hrow + kq * 68);
            ulonglong2 r0 = *(const ulonglong2*)(rrow + kq * 256);
            ulonglong2 r1 = *(const ulonglong2*)(rrow + kq * 256 + 4);
            ulonglong2 r2 = *(const ulonglong2*)(rrow + kq * 256 + 8);
            ulonglong2 r3 = *(const ulonglong2*)(rrow + kq * 256 + 12);
            ffma2(a0, r0.x, hh.x); ffma2(a0, r0.y, hh.y);
            ffma2(a1, r1.x, hh.x); ffma2(a1, r1.y, hh.y);
            ffma2(a2, r2.x, hh.x); ffma2(a2, r2.y, hh.y);
            ffma2(a3, r3.x, hh.x); ffma2(a3, r3.y, hh.y);
        }

        const float* xb = xzs + (t & 1) * 1088 + u_l * 17 + b_l;
        float2 p;
        p = unpack2(a0); float z1 = p.x + p.y + xb[0];
        p = unpack2(a1); float z2 = p.x + p.y + xb[272];
        p = unpack2(a2); float z3 = p.x + p.y + xb[544];
        p = unpack2(a3); float z4 = p.x + p.y + xb[816];

        float v1 = ftanh(z1);
        float v2 = fsig(z2);
        float v3 = fsig(z3);
        float v4 = fsig(z4);
        c_state = v1 * v2 + v3 * c_state;
        float hnew = v4 * ftanh(c_state);

        __stcg(&g_h[(t + 1) & 1][b0 + b_l][u0 + u_l], hnew);

        if (t + 1 < TSTEPS) {
            float vv[4] = {xnext.x, xnext.y, xnext.z, xnext.w};
            float* dst = xzs + ((t + 1) & 1) * 1088;
#pragma unroll
            for (int j = 0; j < 4; j++)
                dst[pg * 272 + (pq * 4 + j) * 17 + pb] = vv[j];
        }

        // ---- flag-line barrier (32 CTAs per batch group, monotonic flags)
        __syncthreads();
        if (tid == 0) {
            __threadfence();
            asm volatile("st.release.gpu.global.u32 [%0], %1;"
                         :: "l"(myflag), "r"((unsigned)(t + 1)) : "memory");
        }
        {
            const unsigned target = (unsigned)(t + 1);
            unsigned v;
            do {
                asm volatile("ld.acquire.gpu.global.u32 %0, [%1];"
                             : "=r"(v) : "l"(flagline + (tid & 31)) : "memory");
            } while (__any_sync(0xffffffffu, v < target));
        }
        __threadfence();
        __syncthreads();
    }
}

// -------- final dense + softmax ---------------------------------------------
__global__ void fc_softmax(const float* __restrict__ fc_w,
                           const float* __restrict__ fc_b,
                           float* __restrict__ out)
{
    const int b = blockIdx.x;
    const int l = threadIdx.x;
    float a0 = 0.f, a1 = 0.f, a2 = 0.f, a3 = 0.f;
    const float* hg = &g_h[0][b][0];   // final h in parity 0
    for (int k = l * 16; k < l * 16 + 16; k += 4) {
        float4 hv = *(const float4*)(hg + k);
        float hx[4] = {hv.x, hv.y, hv.z, hv.w};
#pragma unroll
        for (int q = 0; q < 4; q++) {
            float4 wv = *(const float4*)&fc_w[(k + q) * 4];
            a0 += hx[q] * wv.x; a1 += hx[q] * wv.y;
            a2 += hx[q] * wv.z; a3 += hx[q] * wv.w;
        }
    }
#pragma unroll
    for (int o = 16; o > 0; o >>= 1) {
        a0 += __shfl_down_sync(0xffffffffu, a0, o);
        a1 += __shfl_down_sync(0xffffffffu, a1, o);
        a2 += __shfl_down_sync(0xffffffffu, a2, o);
        a3 += __shfl_down_sync(0xffffffffu, a3, o);
    }
    if (l == 0) {
        float z0 = a0 + fc_b[0], z1 = a1 + fc_b[1];
        float z2 = a2 + fc_b[2], z3 = a3 + fc_b[3];
        float m = fmaxf(fmaxf(z0, z1), fmaxf(z2, z3));
        float e0 = __expf(z0 - m), e1 = __expf(z1 - m);
        float e2 = __expf(z2 - m), e3 = __expf(z3 - m);
        float inv = __fdividef(1.f, e0 + e1 + e2 + e3);
        out[b * 4 + 0] = e0 * inv;
        out[b * 4 + 1] = e1 * inv;
        out[b * 4 + 2] = e2 * inv;
        out[b * 4 + 3] = e3 * inv;
    }
}

// ---------------------------------------------------------------------------
extern "C" void kernel_launch(void* const* d_in, const int* in_sizes, int n_in,
                              void* d_out, int out_size)
{
    const float* tx      = (const float*)d_in[0];
    const float* kernelW = (const float*)d_in[1];
    const float* R       = (const float*)d_in[2];
    const float* bias    = (const float*)d_in[3];
    const float* fc_w    = (const float*)d_in[4];
    const float* fc_b    = (const float*)d_in[5];
    float* out           = (float*)d_out;

    cudaFuncSetAttribute(lstm_recur,
                         cudaFuncAttributeMaxDynamicSharedMemorySize, SM_BYTES);

    init_kernel<<<(2 * BATCH * UNITS + 255) / 256, 256>>>();
    sgemm_bias<<<dim3(FOURU / 128, (BATCH * TSTEPS) / 128), 256>>>(tx, kernelW, bias);
    lstm_recur<<<NCTA, TPB, SM_BYTES>>>(R);
    fc_softmax<<<BATCH, 32>>>(fc_w, fc_b, out);
    (void)in_sizes; (void)n_in; (void)out_size;
}

// round 6
// speedup vs baseline: 1.4570x; 1.4570x over previous
#include <cuda_runtime.h>
#include <cuda_bf16.h>
#include <cstdint>

// LSTM  B=64, T=1024, D=512, U=512, OUT=4
#define BATCH    64
#define TSTEPS   1024
#define DIN      512
#define UNITS    512
#define FOURU    2048
#define NCTA     128
#define TPB      256
#define NBG      4
#define GROUP_CTAS 32
#define NMTILE   4096
#define NKSTEP   32

// smem layout (floats) for recurrence
#define SM_R4     0        // [128 kq][16 u][16 e] e=g*4+kl : 32768
#define SM_H4     32768    // [128 kq][68 pad]              : 8704
#define SM_XZ     41472    // [2][4 g][16 u][17 pad]        : 2176
#define SM_FLOATS 43648
#define SM_BYTES  (SM_FLOATS * 4)

__device__ float    g_xz[(size_t)BATCH * TSTEPS * FOURU];          // 512 MB
__device__ uint4    g_Afrag[(size_t)NMTILE * NKSTEP * 2 * 32];     // 134 MB
__device__ uint4    g_Wfrag[(size_t)NKSTEP * 2 * 64 * 32 * 2];     // 8 MB
__device__ float    g_h[2][BATCH][UNITS];                          // batch-major
__device__ unsigned          g_arrive[NBG * 32];
__device__ volatile unsigned g_gen[NBG * 32];

typedef unsigned long long u64t;
__device__ __forceinline__ void ffma2(u64t& d, u64t a, u64t b) {
    asm("fma.rn.f32x2 %0, %1, %2, %0;" : "+l"(d) : "l"(a), "l"(b));
}
__device__ __forceinline__ float2 unpack2(u64t v) {
    float2 f; asm("mov.b64 {%0, %1}, %2;" : "=f"(f.x), "=f"(f.y) : "l"(v)); return f;
}
__device__ __forceinline__ float fsig(float x) {
    return __fdividef(1.f, 1.f + __expf(-x));
}
__device__ __forceinline__ float ftanh(float x) {
    return 1.f - __fdividef(2.f, __expf(2.f * x) + 1.f);
}
__device__ __forceinline__ uint32_t pack_split_hi(float a, float b) {
    __nv_bfloat16 ha = __float2bfloat16(a), hb = __float2bfloat16(b);
    return (uint32_t)*(uint16_t*)&ha | ((uint32_t)*(uint16_t*)&hb << 16);
}
__device__ __forceinline__ uint32_t pack_split_lo(float a, float b) {
    __nv_bfloat16 ha = __float2bfloat16(a), hb = __float2bfloat16(b);
    __nv_bfloat16 la = __float2bfloat16(a - __bfloat162float(ha));
    __nv_bfloat16 lb = __float2bfloat16(b - __bfloat162float(hb));
    return (uint32_t)*(uint16_t*)&la | ((uint32_t)*(uint16_t*)&lb << 16);
}

__global__ void init_kernel() {
    int i = blockIdx.x * blockDim.x + threadIdx.x;
    if (i < 2 * BATCH * UNITS) ((float*)g_h)[i] = 0.f;
    if (i < NBG * 32) { g_arrive[i] = 0u; g_gen[i] = 0u; }
}

// ---- prep A: tx -> fragment-ordered split-bf16 uint4 ----------------------
// Afrag[( (mt*32+ks)*2 + s)*32 + t] : uint4 regs r0..r3 of mma A fragment
__global__ __launch_bounds__(256) void prep_A(const float* __restrict__ A) {
    int f = blockIdx.x * 256 + threadIdx.x;         // 4,194,304 threads
    int t = f & 31, ks = (f >> 5) & 31, mt = f >> 10;
    uint32_t hi[4], lo[4];
#pragma unroll
    for (int r = 0; r < 4; r++) {
        int m  = mt * 16 + (r & 1) * 8 + (t >> 2);
        int k0 = ks * 16 + ((r & 2) << 2) + ((t & 3) << 1);
        float2 av = *(const float2*)(A + (size_t)m * DIN + k0);
        hi[r] = pack_split_hi(av.x, av.y);
        lo[r] = pack_split_lo(av.x, av.y);
    }
    size_t ib = ((size_t)mt * 32 + ks) * 2;
    g_Afrag[ib * 32 + t]       = make_uint4(hi[0], hi[1], hi[2], hi[3]);
    g_Afrag[(ib + 1) * 32 + t] = make_uint4(lo[0], lo[1], lo[2], lo[3]);
}

// ---- prep W: kernel -> fragment-ordered split-bf16 uint4 ------------------
// Wfrag[ (((ks*2+s)*64+ngrp)*32+t)*2 + q ] : q=0 nblk{0,1}, q=1 nblk{2,3}
__global__ __launch_bounds__(256) void prep_W(const float* __restrict__ W) {
    int f = blockIdx.x * 256 + threadIdx.x;         // 65,536 threads
    int t = f & 31, ngrp = (f >> 5) & 63, ks = f >> 11;
    uint32_t hi[8], lo[8];
#pragma unroll
    for (int nblk = 0; nblk < 4; nblk++)
#pragma unroll
        for (int reg = 0; reg < 2; reg++) {
            int k0 = ks * 16 + reg * 8 + (t & 3) * 2;
            int n  = ngrp * 32 + nblk * 8 + (t >> 2);
            float w0 = W[(size_t)k0 * FOURU + n];
            float w1 = W[(size_t)(k0 + 1) * FOURU + n];
            hi[nblk * 2 + reg] = pack_split_hi(w0, w1);
            lo[nblk * 2 + reg] = pack_split_lo(w0, w1);
        }
    size_t wb = (((size_t)ks * 2 + 0) * 64 + ngrp) * 32 + t;
    size_t wl = (((size_t)ks * 2 + 1) * 64 + ngrp) * 32 + t;
    g_Wfrag[wb * 2]     = make_uint4(hi[0], hi[1], hi[2], hi[3]);
    g_Wfrag[wb * 2 + 1] = make_uint4(hi[4], hi[5], hi[6], hi[7]);
    g_Wfrag[wl * 2]     = make_uint4(lo[0], lo[1], lo[2], lo[3]);
    g_Wfrag[wl * 2 + 1] = make_uint4(lo[4], lo[5], lo[6], lo[7]);
}

#define MMA16816(c, a, b0v, b1v)                                              \
    asm volatile(                                                             \
        "mma.sync.aligned.m16n8k16.row.col.f32.bf16.bf16.f32 "                \
        "{%0,%1,%2,%3}, {%4,%5,%6,%7}, {%8,%9}, {%0,%1,%2,%3};"               \
        : "+f"((c)[0]), "+f"((c)[1]), "+f"((c)[2]), "+f"((c)[3])              \
        : "r"((a).x), "r"((a).y), "r"((a).z), "r"((a).w),                     \
          "r"(b0v), "r"(b1v))

// ---- GEMM: g_xz = A @ W + bias via split-bf16 mma (3 mmas per tile) --------
// grid (16, 512), 256 thr = 8 warps (wm 2 x wn 4); warp = 64 rows x 32 cols.
__global__ __launch_bounds__(256) void gemm_mma(const float* __restrict__ bias) {
    const int tid = threadIdx.x;
    const int t = tid & 31, wid = tid >> 5;
    const int wm = wid & 1, wn = wid >> 1;
    const int mtb = blockIdx.y * 8 + wm * 4;
    const int ngrp = blockIdx.x * 4 + wn;

    float acc[4][4][4];
#pragma unroll
    for (int mi = 0; mi < 4; mi++)
#pragma unroll
        for (int ni = 0; ni < 4; ni++)
#pragma unroll
            for (int c = 0; c < 4; c++) acc[mi][ni][c] = 0.f;

#pragma unroll 2
    for (int ks = 0; ks < NKSTEP; ks++) {
        uint4 ah[4], al[4];
#pragma unroll
        for (int mi = 0; mi < 4; mi++) {
            size_t ib = ((size_t)(mtb + mi) * 32 + ks) * 2;
            ah[mi] = g_Afrag[ib * 32 + t];
            al[mi] = g_Afrag[(ib + 1) * 32 + t];
        }
        size_t wb = (((size_t)ks * 2 + 0) * 64 + ngrp) * 32 + t;
        size_t wl = (((size_t)ks * 2 + 1) * 64 + ngrp) * 32 + t;
        uint4 bh0 = g_Wfrag[wb * 2], bh1 = g_Wfrag[wb * 2 + 1];
        uint4 bl0 = g_Wfrag[wl * 2], bl1 = g_Wfrag[wl * 2 + 1];
        uint32_t bh[8] = {bh0.x, bh0.y, bh0.z, bh0.w, bh1.x, bh1.y, bh1.z, bh1.w};
        uint32_t bl[8] = {bl0.x, bl0.y, bl0.z, bl0.w, bl1.x, bl1.y, bl1.z, bl1.w};

#pragma unroll
        for (int mi = 0; mi < 4; mi++)
#pragma unroll
            for (int ni = 0; ni < 4; ni++) {
                MMA16816(acc[mi][ni], ah[mi], bh[ni * 2], bh[ni * 2 + 1]);
                MMA16816(acc[mi][ni], ah[mi], bl[ni * 2], bl[ni * 2 + 1]);
                MMA16816(acc[mi][ni], al[mi], bh[ni * 2], bh[ni * 2 + 1]);
            }
    }

    const int colbase = blockIdx.x * 128 + wn * 32 + (t & 3) * 2;
    const int rowbase = blockIdx.y * 128 + wm * 64 + (t >> 2);
    float2 bv[4];
#pragma unroll
    for (int ni = 0; ni < 4; ni++)
        bv[ni] = *(const float2*)(bias + colbase + ni * 8);
#pragma unroll
    for (int mi = 0; mi < 4; mi++) {
        int r0 = rowbase + mi * 16;
#pragma unroll
        for (int ni = 0; ni < 4; ni++) {
            int col = colbase + ni * 8;
            float2 o0 = make_float2(acc[mi][ni][0] + bv[ni].x,
                                    acc[mi][ni][1] + bv[ni].y);
            float2 o1 = make_float2(acc[mi][ni][2] + bv[ni].x,
                                    acc[mi][ni][3] + bv[ni].y);
            __stcs((float2*)(g_xz + (size_t)r0 * FOURU + col), o0);
            __stcs((float2*)(g_xz + (size_t)(r0 + 8) * FOURU + col), o1);
        }
    }
}

// ---- persistent LSTM recurrence (R2 barrier + vectorized staging) ----------
__global__ __launch_bounds__(TPB, 1) void lstm_recur(const float* __restrict__ R)
{
    extern __shared__ float sm[];
    float* R4  = sm + SM_R4;
    float* h4  = sm + SM_H4;
    float* xzs = sm + SM_XZ;

    const int tid = threadIdx.x;
    const int ug = blockIdx.x >> 2, bg = blockIdx.x & 3;
    const int u0 = ug * 16, b0 = bg * 16;
    const int b_l = tid & 15, u_l = tid >> 4;

    for (int i = tid; i < 32768; i += TPB) {
        int kq = i >> 8, u = (i >> 4) & 15, e = i & 15, g = e >> 2, kl = e & 3;
        R4[i] = R[(size_t)(kq * 4 + kl) * FOURU + g * UNITS + u0 + u];
    }

    const int pb = tid >> 4, pg = (tid >> 2) & 3, pq = tid & 3;
    const float* xz_thread = g_xz + (size_t)(b0 + pb) * TSTEPS * FOURU
                             + pg * UNITS + u0 + pq * 4;
    {
        float4 v = __ldcs((const float4*)xz_thread);
        float vv[4] = {v.x, v.y, v.z, v.w};
#pragma unroll
        for (int j = 0; j < 4; j++)
            xzs[pg * 272 + (pq * 4 + j) * 17 + pb] = vv[j];
    }
    __syncthreads();

    const int sb = tid >> 4, kqb = tid & 15;
    unsigned* arrive = &g_arrive[bg * 32];
    volatile unsigned* gen = &g_gen[bg * 32];

    float c_state = 0.f;

    for (int t = 0; t < TSTEPS; t++) {
        float4 xnext = make_float4(0.f, 0.f, 0.f, 0.f);
        if (t + 1 < TSTEPS)
            xnext = __ldcs((const float4*)(xz_thread + (size_t)(t + 1) * FOURU));

        const float* hsrc = &g_h[t & 1][b0 + sb][0];
        float4 hq[8];
#pragma unroll
        for (int r = 0; r < 8; r++)
            hq[r] = __ldcg((const float4*)(hsrc + (kqb + 16 * r) * 4));

#pragma unroll
        for (int r = 0; r < 4; r++)
            *(float4*)&h4[(kqb + 16 * r) * 68 + sb * 4] = hq[r];
        __syncthreads();

        u64t a0 = 0ull, a1 = 0ull, a2 = 0ull, a3 = 0ull;
        const float* hrow = h4 + b_l * 4;
        const float* rrow = R4 + u_l * 16;
#pragma unroll 8
        for (int kq = 0; kq < 64; kq++) {
            ulonglong2 hh = *(const ulonglong2*)(hrow + kq * 68);
            ulonglong2 r0 = *(const ulonglong2*)(rrow + kq * 256);
            ulonglong2 r1 = *(const ulonglong2*)(rrow + kq * 256 + 4);
            ulonglong2 r2 = *(const ulonglong2*)(rrow + kq * 256 + 8);
            ulonglong2 r3 = *(const ulonglong2*)(rrow + kq * 256 + 12);
            ffma2(a0, r0.x, hh.x); ffma2(a0, r0.y, hh.y);
            ffma2(a1, r1.x, hh.x); ffma2(a1, r1.y, hh.y);
            ffma2(a2, r2.x, hh.x); ffma2(a2, r2.y, hh.y);
            ffma2(a3, r3.x, hh.x); ffma2(a3, r3.y, hh.y);
        }

#pragma unroll
        for (int r = 4; r < 8; r++)
            *(float4*)&h4[(kqb + 16 * r) * 68 + sb * 4] = hq[r];
        __syncthreads();

#pragma unroll 8
        for (int kq = 64; kq < 128; kq++) {
            ulonglong2 hh = *(const ulonglong2*)(hrow + kq * 68);
            ulonglong2 r0 = *(const ulonglong2*)(rrow + kq * 256);
            ulonglong2 r1 = *(const ulonglong2*)(rrow + kq * 256 + 4);
            ulonglong2 r2 = *(const ulonglong2*)(rrow + kq * 256 + 8);
            ulonglong2 r3 = *(const ulonglong2*)(rrow + kq * 256 + 12);
            ffma2(a0, r0.x, hh.x); ffma2(a0, r0.y, hh.y);
            ffma2(a1, r1.x, hh.x); ffma2(a1, r1.y, hh.y);
            ffma2(a2, r2.x, hh.x); ffma2(a2, r2.y, hh.y);
            ffma2(a3, r3.x, hh.x); ffma2(a3, r3.y, hh.y);
        }

        const float* xb = xzs + (t & 1) * 1088 + u_l * 17 + b_l;
        float2 p;
        p = unpack2(a0); float z1 = p.x + p.y + xb[0];
        p = unpack2(a1); float z2 = p.x + p.y + xb[272];
        p = unpack2(a2); float z3 = p.x + p.y + xb[544];
        p = unpack2(a3); float z4 = p.x + p.y + xb[816];

        float v1 = ftanh(z1);
        float v2 = fsig(z2);
        float v3 = fsig(z3);
        float v4 = fsig(z4);
        c_state = v1 * v2 + v3 * c_state;
        float hnew = v4 * ftanh(c_state);

        __stcg(&g_h[(t + 1) & 1][b0 + b_l][u0 + u_l], hnew);

        if (t + 1 < TSTEPS) {
            float vv[4] = {xnext.x, xnext.y, xnext.z, xnext.w};
            float* dst = xzs + ((t + 1) & 1) * 1088;
#pragma unroll
            for (int j = 0; j < 4; j++)
                dst[pg * 272 + (pq * 4 + j) * 17 + pb] = vv[j];
        }

        // ---- R2 barrier: atomic arrival + single-waiter gen poll ----
        __syncthreads();
        if (tid == 0) {
            __threadfence();
            unsigned prev = atomicAdd(arrive, 1u);
            if (prev == GROUP_CTAS - 1) {
                atomicExch(arrive, 0u);
                __threadfence();
                *gen = (unsigned)(t + 1);
            } else {
                while (*gen < (unsigned)(t + 1)) { }
            }
            __threadfence();
        }
        __syncthreads();
    }
}

// ---- final dense + softmax --------------------------------------------------
__global__ void fc_softmax(const float* __restrict__ fc_w,
                           const float* __restrict__ fc_b,
                           float* __restrict__ out)
{
    const int b = blockIdx.x;
    const int l = threadIdx.x;
    float a0 = 0.f, a1 = 0.f, a2 = 0.f, a3 = 0.f;
    const float* hg = &g_h[0][b][0];
    for (int k = l * 16; k < l * 16 + 16; k += 4) {
        float4 hv = *(const float4*)(hg + k);
        float hx[4] = {hv.x, hv.y, hv.z, hv.w};
#pragma unroll
        for (int q = 0; q < 4; q++) {
            float4 wv = *(const float4*)&fc_w[(k + q) * 4];
            a0 += hx[q] * wv.x; a1 += hx[q] * wv.y;
            a2 += hx[q] * wv.z; a3 += hx[q] * wv.w;
        }
    }
#pragma unroll
    for (int o = 16; o > 0; o >>= 1) {
        a0 += __shfl_down_sync(0xffffffffu, a0, o);
        a1 += __shfl_down_sync(0xffffffffu, a1, o);
        a2 += __shfl_down_sync(0xffffffffu, a2, o);
        a3 += __shfl_down_sync(0xffffffffu, a3, o);
    }
    if (l == 0) {
        float z0 = a0 + fc_b[0], z1 = a1 + fc_b[1];
        float z2 = a2 + fc_b[2], z3 = a3 + fc_b[3];
        float m = fmaxf(fmaxf(z0, z1), fmaxf(z2, z3));
        float e0 = __expf(z0 - m), e1 = __expf(z1 - m);
        float e2 = __expf(z2 - m), e3 = __expf(z3 - m);
        float inv = __fdividef(1.f, e0 + e1 + e2 + e3);
        out[b * 4 + 0] = e0 * inv;
        out[b * 4 + 1] = e1 * inv;
        out[b * 4 + 2] = e2 * inv;
        out[b * 4 + 3] = e3 * inv;
    }
}

// ---------------------------------------------------------------------------
extern "C" void kernel_launch(void* const* d_in, const int* in_sizes, int n_in,
                              void* d_out, int out_size)
{
    const float* tx      = (const float*)d_in[0];
    const float* kernelW = (const float*)d_in[1];
    const float* R       = (const float*)d_in[2];
    const float* bias    = (const float*)d_in[3];
    const float* fc_w    = (const float*)d_in[4];
    const float* fc_b    = (const float*)d_in[5];
    float* out           = (float*)d_out;

    cudaFuncSetAttribute(lstm_recur,
                         cudaFuncAttributeMaxDynamicSharedMemorySize, SM_BYTES);

    init_kernel<<<(2 * BATCH * UNITS + 255) / 256, 256>>>();
    prep_A<<<16384, 256>>>(tx);
    prep_W<<<256, 256>>>(kernelW);
    gemm_mma<<<dim3(16, 512), 256>>>(bias);
    lstm_recur<<<NCTA, TPB, SM_BYTES>>>(R);
    fc_softmax<<<BATCH, 32>>>(fc_w, fc_b, out);
    (void)in_sizes; (void)n_in; (void)out_size;
}